// round 15
// baseline (speedup 1.0000x reference)
#include <cuda_runtime.h>
#include <math.h>
#include <stdint.h>

#define NT 128                  // threads per block = 4 autonomous warps
#define MPB 128                 // matrices per tile (1 per thread)
#define TILE_FLOATS (MPB * 9)   // 1152 floats per stream per tile
#define TILE_F4 (TILE_FLOATS/4) // 288 float4
#define WSLICE_F4 (TILE_F4/4)   // 72 float4 per warp per stream
#define GRID_BLOCKS 1332        // 9 blocks/SM x 148 SMs
#define JITTER 1e-6f
#define REPS 1e-26f             // degeneracy bias: orthogonality err <= eps/(2*r2)

// ---------------- cp.async helpers ----------------
__device__ __forceinline__ uint32_t smem_u32(const void* p) {
    uint32_t a;
    asm("{ .reg .u64 t; cvta.to.shared.u64 t, %1; cvt.u32.u64 %0, t; }"
        : "=r"(a) : "l"(p));
    return a;
}
__device__ __forceinline__ void cp16(uint32_t dst, const void* src) {
    asm volatile("cp.async.cg.shared.global [%0], [%1], 16;"
                 :: "r"(dst), "l"(src));
}
__device__ __forceinline__ void cp_commit() {
    asm volatile("cp.async.commit_group;");
}
template <int N>
__device__ __forceinline__ void cp_wait() {
    asm volatile("cp.async.wait_group %0;" :: "n"(N));
}
// Streaming store: output is never re-read -> evict-first, keep L2 for inputs.
__device__ __forceinline__ void stcs4(float4* p, float4 v) {
    asm volatile("st.global.cs.v4.f32 [%0], {%1, %2, %3, %4};"
                 :: "l"(p), "f"(v.x), "f"(v.y), "f"(v.z), "f"(v.w));
}

// ---------------- math (frozen: rel_err 8.65e-7) ----------------
// MUFU rsqrt (~2^-22). MUFU rt is per WARP-instruction: ~10us chip-busy
// for all 20 rsqrts/matrix, fully hidden (R12 verified).
__device__ __forceinline__ float rsqrt_mufu(float x) {
    float y;
    asm("rsqrt.approx.f32 %0, %1;" : "=f"(y) : "f"(x));
    return y;
}

// EXACT annihilating Givens rotation on plane (p,q), division-free.
// 9 rotations (3 sweeps) is the verified accuracy floor (6 -> 3.5e-3 FAIL).
template <bool OFFDIAG>
__device__ __forceinline__ void jrot(float& app, float& aqq, float& apq,
                                     float& apr, float& aqr,
                                     float vp[3], float vq[3]) {
    float d  = app - aqq;
    float r2 = fmaf(d, d, fmaf(4.0f * apq, apq, REPS));
    float w  = rsqrt_mufu(r2);
    float cos2t = fabsf(d) * w;                      // <= 1 always
    float sin2t = 2.0f * apq * copysignf(w, d);      // <= 1 always
    float u     = fmaf(0.5f, cos2t, 0.5f);           // in [0.5, 1]
    float invc  = rsqrt_mufu(u);
    float c = u * invc;                              // sqrt(u)
    float s = 0.5f * sin2t * invc;

    float half_sum = 0.5f * (app + aqq);
    float t_pp = fmaf(0.5f * d, cos2t, fmaf(apq, sin2t, half_sum));
    float t_qq = fmaf(2.0f, half_sum, -t_pp);        // trace preservation
    app = t_pp; aqq = t_qq; apq = 0.0f;
    if (OFFDIAG) {
        float t_pr = fmaf(c, apr, s * aqr);
        float t_qr = fmaf(c, aqr, -s * apr);
        apr = t_pr; aqr = t_qr;
    }
#pragma unroll
    for (int i = 0; i < 3; i++) {
        float a = vp[i], b = vq[i];
        vp[i] = fmaf(c, a, s * b);
        vq[i] = fmaf(c, b, -s * a);
    }
}

__device__ __forceinline__ void cross3(const float a[3], const float b[3], float o[3]) {
    o[0] = fmaf(a[1], b[2], -a[2] * b[1]);
    o[1] = fmaf(a[2], b[0], -a[0] * b[2]);
    o[2] = fmaf(a[0], b[1], -a[1] * b[0]);
}

// ---------------- kernel ----------------
// WARP-AUTONOMOUS: each warp owns a 32-matrix slice of every tile. All
// cp.async destinations, fuse reads (tid*9 stays inside warp wid's 1152B
// slice), rbuf writes, and output float4s partition per warp -> zero
// cross-warp data flow -> NO __syncthreads anywhere. Each lane waits on
// its own cp.async group; __syncwarp() then gives warp-wide visibility.
__global__ void __launch_bounds__(NT, 9)   // 9 blocks/SM = 36 decoupled warps
orientation_bfn_kernel(const float* __restrict__ Rc,
                       const float* __restrict__ tarr,
                       const float* __restrict__ nz,
                       const float* __restrict__ ep,
                       float* __restrict__ out,
                       int ntiles, int tshift, int tiles_per_t) {
    __shared__ float4 raw[3][TILE_F4];   // 13.8 KB
    __shared__ float4 rbuf[TILE_F4];     //  4.6 KB

    const int tid  = threadIdx.x;
    const int lane = tid & 31;
    const int wb   = (tid >> 5) * WSLICE_F4;   // warp slice base (float4)

    // Prologue: prefetch this warp's slice of the first tile.
    int tile0 = blockIdx.x;
    if (tile0 < ntiles) {
        uint32_t sb = smem_u32(&raw[0][0]);
        const float4* r4 = reinterpret_cast<const float4*>(Rc) + (long long)tile0 * TILE_F4 + wb;
        const float4* n4 = reinterpret_cast<const float4*>(nz) + (long long)tile0 * TILE_F4 + wb;
        const float4* e4 = reinterpret_cast<const float4*>(ep) + (long long)tile0 * TILE_F4 + wb;
        for (int i = lane; i < WSLICE_F4; i += 32) {
            cp16(sb + (0 * TILE_F4 + wb + i) * 16, r4 + i);
            cp16(sb + (1 * TILE_F4 + wb + i) * 16, n4 + i);
            cp16(sb + (2 * TILE_F4 + wb + i) * 16, e4 + i);
        }
        cp_commit();
    }

    for (int tile = tile0; tile < ntiles; tile += GRID_BLOCKS) {
        // t load overlaps the async-copy wait.
        const int t_idx = (tshift >= 0) ? (tile >> tshift) : (tile / tiles_per_t);
        const float tval = __ldg(&tarr[t_idx]);
        const float stv  = sqrtf(tval);

        cp_wait<0>();       // own group done
        __syncwarp();       // all lanes' groups done + warp-scope visibility

        // Fuse F = t*R + sqrt(t)*noise + JITTER*eps into registers
        // (stride 9 -> conflict-free; reads stay inside this warp's slice).
        const float* rr = reinterpret_cast<const float*>(&raw[0][0]) + tid * 9;
        const float* rn = reinterpret_cast<const float*>(&raw[1][0]) + tid * 9;
        const float* re = reinterpret_cast<const float*>(&raw[2][0]) + tid * 9;
        float F[9];
#pragma unroll
        for (int k = 0; k < 9; k++)
            F[k] = fmaf(tval, rr[k], fmaf(stv, rn[k], JITTER * re[k]));

        __syncwarp();       // all fuse reads done -> warp slice reusable

        // Issue next tile's prefetch for this warp's slice; latency hides
        // under the Jacobi compute below.
        const int nxt_tile = tile + GRID_BLOCKS;
        if (nxt_tile < ntiles) {
            uint32_t sb = smem_u32(&raw[0][0]);
            const float4* r4 = reinterpret_cast<const float4*>(Rc) + (long long)nxt_tile * TILE_F4 + wb;
            const float4* n4 = reinterpret_cast<const float4*>(nz) + (long long)nxt_tile * TILE_F4 + wb;
            const float4* e4 = reinterpret_cast<const float4*>(ep) + (long long)nxt_tile * TILE_F4 + wb;
            for (int i = lane; i < WSLICE_F4; i += 32) {
                cp16(sb + (0 * TILE_F4 + wb + i) * 16, r4 + i);
                cp16(sb + (1 * TILE_F4 + wb + i) * 16, n4 + i);
                cp16(sb + (2 * TILE_F4 + wb + i) * 16, e4 + i);
            }
            cp_commit();
        }

        // A = F^T F
        float a00 = F[0]*F[0] + F[3]*F[3] + F[6]*F[6];
        float a01 = F[0]*F[1] + F[3]*F[4] + F[6]*F[7];
        float a02 = F[0]*F[2] + F[3]*F[5] + F[6]*F[8];
        float a11 = F[1]*F[1] + F[4]*F[4] + F[7]*F[7];
        float a12 = F[1]*F[2] + F[4]*F[5] + F[7]*F[8];
        float a22 = F[2]*F[2] + F[5]*F[5] + F[8]*F[8];

        float V0[3] = {1.f, 0.f, 0.f};
        float V1[3] = {0.f, 1.f, 0.f};
        float V2[3] = {0.f, 0.f, 1.f};

        // 3 exact cyclic sweeps (verified floor); final rotation skips dead
        // off-diagonal updates.
        jrot<true >(a00, a11, a01, a02, a12, V0, V1);
        jrot<true >(a00, a22, a02, a01, a12, V0, V2);
        jrot<true >(a11, a22, a12, a01, a02, V1, V2);
        jrot<true >(a00, a11, a01, a02, a12, V0, V1);
        jrot<true >(a00, a22, a02, a01, a12, V0, V2);
        jrot<true >(a11, a22, a12, a01, a02, V1, V2);
        jrot<true >(a00, a11, a01, a02, a12, V0, V1);
        jrot<true >(a00, a22, a02, a01, a12, V0, V2);
        jrot<false>(a11, a22, a12, a01, a02, V1, V2);

        // Pick eigenvectors of the largest and middle eigenvalues directly.
        bool gt01 = a00 >= a11;
        bool gt02 = a00 >= a22;
        bool gt12 = a11 >= a22;
        bool max0 = gt01 && gt02;
        bool max1 = (!gt01) && gt12;
        float vmax[3], vmid[3], v3[3];
#pragma unroll
        for (int i = 0; i < 3; i++) {
            float innerMax = gt12 ? V1[i] : V2[i];   // largest among {1,2}
            vmax[i] = max0 ? V0[i] : innerMax;
            float mid_if_max1 = gt02 ? V0[i] : V2[i];
            float mid_if_max2 = gt01 ? V0[i] : V1[i];
            vmid[i] = max0 ? innerMax : (max1 ? mid_if_max1 : mid_if_max2);
        }
        cross3(vmax, vmid, v3);   // right-handed third column, det(V)=+1

        // b_i = F v_i, Gram-Schmidt -> U
        float b1[3], b2[3];
#pragma unroll
        for (int i = 0; i < 3; i++) {
            b1[i] = fmaf(F[3*i+0], vmax[0], fmaf(F[3*i+1], vmax[1], F[3*i+2] * vmax[2]));
            b2[i] = fmaf(F[3*i+0], vmid[0], fmaf(F[3*i+1], vmid[1], F[3*i+2] * vmid[2]));
        }
        float u1[3], u2[3], u3[3];
        float inv1 = rsqrt_mufu(b1[0]*b1[0] + b1[1]*b1[1] + b1[2]*b1[2] + REPS);
#pragma unroll
        for (int i = 0; i < 3; i++) u1[i] = b1[i] * inv1;
        float proj = fmaf(u1[0], b2[0], fmaf(u1[1], b2[1], u1[2] * b2[2]));
#pragma unroll
        for (int i = 0; i < 3; i++) b2[i] = fmaf(-proj, u1[i], b2[i]);
        float inv2 = rsqrt_mufu(b2[0]*b2[0] + b2[1]*b2[1] + b2[2]*b2[2] + REPS);
#pragma unroll
        for (int i = 0; i < 3; i++) u2[i] = b2[i] * inv2;
        cross3(u1, u2, u3);   // det(U)=+1; smallest-sigma flip implicit

        // R = U V^T into this thread's own rbuf slot (inside warp slice).
        float* Rp = reinterpret_cast<float*>(&rbuf[0]) + tid * 9;
#pragma unroll
        for (int i = 0; i < 3; i++)
#pragma unroll
            for (int k = 0; k < 3; k++)
                Rp[3*i + k] = fmaf(u1[i], vmax[k], fmaf(u2[i], vmid[k], u3[i] * v3[k]));

        __syncwarp();         // warp slice of rbuf complete

        // Coalesced streaming store of this warp's 1152B output slice.
        float4* o4 = reinterpret_cast<float4*>(out) + (long long)tile * TILE_F4 + wb;
        for (int i = lane; i < WSLICE_F4; i += 32) stcs4(o4 + i, rbuf[wb + i]);
        // Next iteration's post-wait __syncwarp orders these rbuf reads
        // before any lane rewrites the slice.
    }
}

extern "C" void kernel_launch(void* const* d_in, const int* in_sizes, int n_in,
                              void* d_out, int out_size) {
    const float* Rc = (const float*)d_in[0];   // R_clean  (N*L*9)
    const float* t  = (const float*)d_in[1];   // t        (N)
    const float* nz = (const float*)d_in[2];   // noise    (N*L*9)
    const float* ep = (const float*)d_in[3];   // eps_noise(N*L*9)
    float* out = (float*)d_out;

    const int total = in_sizes[0];
    const int mats = total / 9;
    const int N = in_sizes[1];
    const int Lmats = mats / N;
    const int ntiles = mats / MPB;             // 16384

    const int tiles_per_t = Lmats / MPB;       // 64 for the bench shape
    int tshift = -1;
    if (tiles_per_t > 0 && (tiles_per_t & (tiles_per_t - 1)) == 0) {
        tshift = 0;
        while ((1 << tshift) != tiles_per_t) tshift++;
    }

    int blocks = ntiles < GRID_BLOCKS ? ntiles : GRID_BLOCKS;
    orientation_bfn_kernel<<<blocks, NT>>>(Rc, t, nz, ep, out,
                                           ntiles, tshift, tiles_per_t);
}

// round 16
// speedup vs baseline: 1.0706x; 1.0706x over previous
#include <cuda_runtime.h>
#include <math.h>
#include <stdint.h>

#define NT 128                  // threads per block
#define MPB 128                 // matrices per tile (1 per thread)
#define TILE_FLOATS (MPB * 9)   // 1152 floats per stream per tile
#define TILE_F4 (TILE_FLOATS/4) // 288 float4
#define GRID_BLOCKS 1332        // 9 blocks/SM x 148 SMs
#define JITTER 1e-6f
#define REPS 1e-26f             // degeneracy bias: orthogonality err <= eps/(2*r2)

// ---------------- cp.async helpers ----------------
__device__ __forceinline__ uint32_t smem_u32(const void* p) {
    uint32_t a;
    asm("{ .reg .u64 t; cvta.to.shared.u64 t, %1; cvt.u32.u64 %0, t; }"
        : "=r"(a) : "l"(p));
    return a;
}
__device__ __forceinline__ void cp16(uint32_t dst, const void* src) {
    asm volatile("cp.async.cg.shared.global [%0], [%1], 16;"
                 :: "r"(dst), "l"(src));
}
__device__ __forceinline__ void cp_commit() {
    asm volatile("cp.async.commit_group;");
}
template <int N>
__device__ __forceinline__ void cp_wait() {
    asm volatile("cp.async.wait_group %0;" :: "n"(N));
}
// Streaming store: output is never re-read -> evict-first, keep L2 for inputs.
__device__ __forceinline__ void stcs4(float4* p, float4 v) {
    asm volatile("st.global.cs.v4.f32 [%0], {%1, %2, %3, %4};"
                 :: "l"(p), "f"(v.x), "f"(v.y), "f"(v.z), "f"(v.w));
}

// ---------------- math (config frozen: rel_err 8.65e-7) ----------------
// MUFU rsqrt (~2^-22). MUFU rt is per WARP-instruction: ~10us chip-busy
// for all 20 rsqrts/matrix, fully hidden (R12 verified).
__device__ __forceinline__ float rsqrt_mufu(float x) {
    float y;
    asm("rsqrt.approx.f32 %0, %1;" : "=f"(y) : "f"(x));
    return y;
}

// EXACT annihilating Givens: A-update only, emits (c,s) for the V update.
// ws = copysign(w,d) folds the sign handling: cos2t = d*ws = |d|*w,
// g = apq*ws -> s = g*invc, apq*sin2t = 2*g*apq.
// 9 rotations (3 sweeps) is the verified accuracy floor (6 -> 3.5e-3 FAIL).
template <bool OFFDIAG>
__device__ __forceinline__ void jrot_cs(float& app, float& aqq, float& apq,
                                        float& apr, float& aqr,
                                        float& c_out, float& s_out) {
    float d  = app - aqq;
    float r2 = fmaf(d, d, fmaf(4.0f * apq, apq, REPS));
    float w  = rsqrt_mufu(r2);
    float ws = copysignf(w, d);
    float cos2t = d * ws;                            // = |d|*w, in [0,1]
    float g  = apq * ws;                             // sin2t = 2g
    float u  = fmaf(0.5f, cos2t, 0.5f);              // in [0.5, 1]
    float invc = rsqrt_mufu(u);
    float c = u * invc;                              // sqrt(u)
    float s = g * invc;                              // 0.5*sin2t/sqrt(u)
    c_out = c; s_out = s;

    float sum  = app + aqq;
    float t_pp = fmaf(0.5f * d, cos2t, fmaf(g + g, apq, 0.5f * sum));
    app = t_pp;
    aqq = sum - t_pp;                                // trace preservation
    apq = 0.0f;
    if (OFFDIAG) {
        float t_pr = fmaf(c, apr, s * aqr);
        float t_qr = fmaf(c, aqr, -s * apr);
        apr = t_pr; aqr = t_qr;
    }
}

__device__ __forceinline__ void vupd(float c, float s, float vp[3], float vq[3]) {
#pragma unroll
    for (int i = 0; i < 3; i++) {
        float a = vp[i], b = vq[i];
        vp[i] = fmaf(c, a, s * b);
        vq[i] = fmaf(c, b, -s * a);
    }
}

__device__ __forceinline__ void cross3(const float a[3], const float b[3], float o[3]) {
    o[0] = fmaf(a[1], b[2], -a[2] * b[1]);
    o[1] = fmaf(a[2], b[0], -a[0] * b[2]);
    o[2] = fmaf(a[0], b[1], -a[1] * b[0]);
}

// ---------------- kernel ----------------
__global__ void __launch_bounds__(NT, 9)   // 56 regs -> 9 blocks/SM
orientation_bfn_kernel(const float* __restrict__ Rc,
                       const float* __restrict__ tarr,
                       const float* __restrict__ nz,
                       const float* __restrict__ ep,
                       float* __restrict__ out,
                       int ntiles, int tshift, int tiles_per_t) {
    // Single raw staging buffer (13.8 KB) + R staging (4.6 KB) = 18.4 KB.
    __shared__ float4 raw[3][TILE_F4];
    __shared__ float4 rbuf[TILE_F4];

    const int tid = threadIdx.x;

    // Prologue: prefetch first tile.
    int tile0 = blockIdx.x;
    if (tile0 < ntiles) {
        uint32_t sb = smem_u32(&raw[0][0]);
        const float4* r4 = reinterpret_cast<const float4*>(Rc) + (long long)tile0 * TILE_F4;
        const float4* n4 = reinterpret_cast<const float4*>(nz) + (long long)tile0 * TILE_F4;
        const float4* e4 = reinterpret_cast<const float4*>(ep) + (long long)tile0 * TILE_F4;
#pragma unroll
        for (int i = tid; i < TILE_F4; i += NT) {
            cp16(sb + (0 * TILE_F4 + i) * 16, r4 + i);
            cp16(sb + (1 * TILE_F4 + i) * 16, n4 + i);
            cp16(sb + (2 * TILE_F4 + i) * 16, e4 + i);
        }
        cp_commit();
    }

    for (int tile = tile0; tile < ntiles; tile += GRID_BLOCKS) {
        // t load overlaps the async-copy wait.
        const int t_idx = (tshift >= 0) ? (tile >> tshift) : (tile / tiles_per_t);
        const float tval = __ldg(&tarr[t_idx]);
        const float stv  = sqrtf(tval);

        cp_wait<0>();
        __syncthreads();    // raw tile visible to all threads

        // Drain raw buffer: F = t*R + sqrt(t)*noise + JITTER*eps into regs
        // (stride 9 across banks -> conflict-free).
        const float* rr = reinterpret_cast<const float*>(&raw[0][0]) + tid * 9;
        const float* rn = reinterpret_cast<const float*>(&raw[1][0]) + tid * 9;
        const float* re = reinterpret_cast<const float*>(&raw[2][0]) + tid * 9;
        float F[9];
#pragma unroll
        for (int k = 0; k < 9; k++)
            F[k] = fmaf(tval, rr[k], fmaf(stv, rn[k], JITTER * re[k]));

        __syncthreads();    // all fuse reads done -> raw buffer reusable

        // Issue next tile's prefetch NOW; latency hides under Jacobi below.
        const int nxt_tile = tile + GRID_BLOCKS;
        if (nxt_tile < ntiles) {
            uint32_t sb = smem_u32(&raw[0][0]);
            const float4* r4 = reinterpret_cast<const float4*>(Rc) + (long long)nxt_tile * TILE_F4;
            const float4* n4 = reinterpret_cast<const float4*>(nz) + (long long)nxt_tile * TILE_F4;
            const float4* e4 = reinterpret_cast<const float4*>(ep) + (long long)nxt_tile * TILE_F4;
#pragma unroll
            for (int i = tid; i < TILE_F4; i += NT) {
                cp16(sb + (0 * TILE_F4 + i) * 16, r4 + i);
                cp16(sb + (1 * TILE_F4 + i) * 16, n4 + i);
                cp16(sb + (2 * TILE_F4 + i) * 16, e4 + i);
            }
            cp_commit();
        }

        // A = F^T F
        float a00 = F[0]*F[0] + F[3]*F[3] + F[6]*F[6];
        float a01 = F[0]*F[1] + F[3]*F[4] + F[6]*F[7];
        float a02 = F[0]*F[2] + F[3]*F[5] + F[6]*F[8];
        float a11 = F[1]*F[1] + F[4]*F[4] + F[7]*F[7];
        float a12 = F[1]*F[2] + F[4]*F[5] + F[7]*F[8];
        float a22 = F[2]*F[2] + F[5]*F[5] + F[8]*F[8];

        float c1, s1, c2, s2, c3, s3;

        // Sweep 1 with specialized V (V starts at identity, so rotations
        // 1-2 yield closed-form V columns: saves 2 full vupds):
        jrot_cs<true>(a00, a11, a01, a02, a12, c1, s1);   // plane (0,1)
        jrot_cs<true>(a00, a22, a02, a01, a12, c2, s2);   // plane (0,2)
        float V0[3] = { c2 * c1,  c2 * s1, s2 };
        float V1[3] = { -s1,      c1,      0.f };
        float V2[3] = { -s2 * c1, -s2 * s1, c2 };
        jrot_cs<true>(a11, a22, a12, a01, a02, c3, s3);   // plane (1,2)
        vupd(c3, s3, V1, V2);

        // Sweeps 2-3 (general); final rotation skips dead off-diag updates.
        jrot_cs<true >(a00, a11, a01, a02, a12, c1, s1); vupd(c1, s1, V0, V1);
        jrot_cs<true >(a00, a22, a02, a01, a12, c1, s1); vupd(c1, s1, V0, V2);
        jrot_cs<true >(a11, a22, a12, a01, a02, c1, s1); vupd(c1, s1, V1, V2);
        jrot_cs<true >(a00, a11, a01, a02, a12, c1, s1); vupd(c1, s1, V0, V1);
        jrot_cs<true >(a00, a22, a02, a01, a12, c1, s1); vupd(c1, s1, V0, V2);
        jrot_cs<false>(a11, a22, a12, a01, a02, c1, s1); vupd(c1, s1, V1, V2);

        // Pick eigenvectors of the largest and middle eigenvalues directly.
        bool gt01 = a00 >= a11;
        bool gt02 = a00 >= a22;
        bool gt12 = a11 >= a22;
        bool max0 = gt01 && gt02;
        bool max1 = (!gt01) && gt12;
        float vmax[3], vmid[3], v3[3];
#pragma unroll
        for (int i = 0; i < 3; i++) {
            float innerMax = gt12 ? V1[i] : V2[i];   // largest among {1,2}
            vmax[i] = max0 ? V0[i] : innerMax;
            float mid_if_max1 = gt02 ? V0[i] : V2[i];
            float mid_if_max2 = gt01 ? V0[i] : V1[i];
            vmid[i] = max0 ? innerMax : (max1 ? mid_if_max1 : mid_if_max2);
        }
        cross3(vmax, vmid, v3);   // right-handed third column, det(V)=+1

        // b_i = F v_i, Gram-Schmidt -> U, R = U V^T
        float b1[3], b2[3];
#pragma unroll
        for (int i = 0; i < 3; i++) {
            b1[i] = fmaf(F[3*i+0], vmax[0], fmaf(F[3*i+1], vmax[1], F[3*i+2] * vmax[2]));
            b2[i] = fmaf(F[3*i+0], vmid[0], fmaf(F[3*i+1], vmid[1], F[3*i+2] * vmid[2]));
        }
        float u1[3], u2[3], u3[3];
        float inv1 = rsqrt_mufu(b1[0]*b1[0] + b1[1]*b1[1] + b1[2]*b1[2] + REPS);
#pragma unroll
        for (int i = 0; i < 3; i++) u1[i] = b1[i] * inv1;
        float proj = fmaf(u1[0], b2[0], fmaf(u1[1], b2[1], u1[2] * b2[2]));
#pragma unroll
        for (int i = 0; i < 3; i++) b2[i] = fmaf(-proj, u1[i], b2[i]);
        float inv2 = rsqrt_mufu(b2[0]*b2[0] + b2[1]*b2[1] + b2[2]*b2[2] + REPS);
#pragma unroll
        for (int i = 0; i < 3; i++) u2[i] = b2[i] * inv2;
        cross3(u1, u2, u3);   // det(U)=+1; smallest-sigma flip implicit

        // R = U V^T into the R staging buffer (own slot, stride 9).
        float* Rp = reinterpret_cast<float*>(&rbuf[0]) + tid * 9;
#pragma unroll
        for (int i = 0; i < 3; i++)
#pragma unroll
            for (int k = 0; k < 3; k++)
                Rp[3*i + k] = fmaf(u1[i], vmax[k], fmaf(u2[i], vmid[k], u3[i] * v3[k]));

        __syncthreads();      // all R written before cross-thread STG reads

        // Coalesced streaming store (output never re-read -> evict-first).
        float4* o4 = reinterpret_cast<float4*>(out) + (long long)tile * TILE_F4;
#pragma unroll
        for (int i = tid; i < TILE_F4; i += NT) stcs4(o4 + i, rbuf[i]);
    }
}

extern "C" void kernel_launch(void* const* d_in, const int* in_sizes, int n_in,
                              void* d_out, int out_size) {
    const float* Rc = (const float*)d_in[0];   // R_clean  (N*L*9)
    const float* t  = (const float*)d_in[1];   // t        (N)
    const float* nz = (const float*)d_in[2];   // noise    (N*L*9)
    const float* ep = (const float*)d_in[3];   // eps_noise(N*L*9)
    float* out = (float*)d_out;

    const int total = in_sizes[0];
    const int mats = total / 9;
    const int N = in_sizes[1];
    const int Lmats = mats / N;
    const int ntiles = mats / MPB;             // 16384

    const int tiles_per_t = Lmats / MPB;       // 64 for the bench shape
    int tshift = -1;
    if (tiles_per_t > 0 && (tiles_per_t & (tiles_per_t - 1)) == 0) {
        tshift = 0;
        while ((1 << tshift) != tiles_per_t) tshift++;
    }

    int blocks = ntiles < GRID_BLOCKS ? ntiles : GRID_BLOCKS;
    orientation_bfn_kernel<<<blocks, NT>>>(Rc, t, nz, ep, out,
                                           ntiles, tshift, tiles_per_t);
}